// round 4
// baseline (speedup 1.0000x reference)
#include <cuda_runtime.h>
#include <cstdint>

// Hash-grid encoding (instant-NGP style), 2D, bilinear, 8 features.
//
// Layout decision: 2 threads per point. Lane pair (2k, 2k+1) handles point k;
// each lane gathers one float4 (16 B) half of each 32 B table row, so the pair
// coalesces into ONE 128B-line wavefront per point-corner instead of two fully
// divergent accesses. Output stores are perfectly coalesced float4s.

#define HASHMAP_MASK ((1u << 22) - 1u)

__global__ __launch_bounds__(256)
void hashgrid_kernel(const float2* __restrict__ x,
                     const float4* __restrict__ table,   // 2 float4 per table row
                     float4* __restrict__ out,           // 2 float4 per point
                     int n_points)
{
    const unsigned P0 = 73856093u;
    const unsigned P1 = 19349663u;

    int t = blockIdx.x * blockDim.x + threadIdx.x;
    int p = t >> 1;      // point index
    int h = t & 1;       // which float4 half of the 8-feature row
    if (p >= n_points) return;

    float2 xp = __ldg(&x[p]);

    // (x+1)*0.5*1024 == (x+1)*512 exactly (power-of-2 scalings are exact in f32),
    // so indices are bit-identical to the reference.
    float fx = (xp.x + 1.0f) * 512.0f;
    float fy = (xp.y + 1.0f) * 512.0f;

    int ix = (int)fx;            // xs >= 0, trunc == floor == astype(int64)
    int iy = (int)fy;
    float wx = fx - (float)ix;
    float wy = fy - (float)iy;

    // hash = (i*P0) ^ (j*P1) mod 2^22 — low 22 bits of uint32 products match int64.
    unsigned hx0 = (unsigned)ix * P0;
    unsigned hx1 = hx0 + P0;
    unsigned hy0 = (unsigned)iy * P1;
    unsigned hy1 = hy0 + P1;

    unsigned i00 = (hx0 ^ hy0) & HASHMAP_MASK;  // neighbor 0: (i  , j  )
    unsigned i10 = (hx1 ^ hy0) & HASHMAP_MASK;  // neighbor 1: (i+1, j  )
    unsigned i01 = (hx0 ^ hy1) & HASHMAP_MASK;  // neighbor 2: (i  , j+1)
    unsigned i11 = (hx1 ^ hy1) & HASHMAP_MASK;  // neighbor 3: (i+1, j+1)

    float w00 = (1.0f - wx) * (1.0f - wy);
    float w10 = wx * (1.0f - wy);
    float w01 = (1.0f - wx) * wy;
    float w11 = wx * wy;

    // Issue all four gathers back-to-back for MLP=4 before consuming.
    float4 a = __ldg(&table[(size_t)i00 * 2u + h]);
    float4 b = __ldg(&table[(size_t)i10 * 2u + h]);
    float4 c = __ldg(&table[(size_t)i01 * 2u + h]);
    float4 d = __ldg(&table[(size_t)i11 * 2u + h]);

    float4 acc;
    acc.x = a.x * w00 + b.x * w10 + c.x * w01 + d.x * w11;
    acc.y = a.y * w00 + b.y * w10 + c.y * w01 + d.y * w11;
    acc.z = a.z * w00 + b.z * w10 + c.z * w01 + d.z * w11;
    acc.w = a.w * w00 + b.w * w10 + c.w * w01 + d.w * w11;

    out[(size_t)p * 2u + h] = acc;
}

extern "C" void kernel_launch(void* const* d_in, const int* in_sizes, int n_in,
                              void* d_out, int out_size)
{
    const float2* x     = (const float2*)d_in[0];   // (N_POINTS, 2) float32
    const float4* table = (const float4*)d_in[1];   // (2^22, 8)  float32
    float4* out         = (float4*)d_out;           // (N_POINTS, 8) float32

    int n_points = in_sizes[0] / 2;
    long long n_threads = (long long)n_points * 2;
    int block = 256;
    int grid = (int)((n_threads + block - 1) / block);
    if (grid < 1) grid = 1;
    hashgrid_kernel<<<grid, block>>>(x, table, out, n_points);
}

// round 7
// speedup vs baseline: 1.0205x; 1.0205x over previous
#include <cuda_runtime.h>
#include <cstdint>

// Hash-grid encoding (instant-NGP style), 2D, bilinear, 8 features.
//
// Layout (R6): 1 thread per point using native 256-bit accesses (sm_100).
// Each corner gather is one ld.global v8.b32 of the full 32 B table row
// (rows are 32 B aligned -> never split across 128 B lines, so still exactly
// one L1 wavefront per point-corner, the floor for random gathers).
//
// L2 policy (from R4 profile: DRAM 67.9% = 578 MB, ~3x compulsory):
//   - table gathers:  .L2::evict_last   (keep ~34 MB hot set resident)
//   - output stores:  .L2::evict_first  (128 MB write stream must not thrash L2)
// ptxas on sm_100 only allows evict hints on .v8.b32/.v4.b64 — hence this layout.

#define HASHMAP_MASK ((1u << 22) - 1u)

struct F8 { float v[8]; };

__device__ __forceinline__ F8 ldg_row(const float* p) {
    unsigned r0, r1, r2, r3, r4, r5, r6, r7;
    asm("ld.global.nc.L2::evict_last.v8.b32 {%0,%1,%2,%3,%4,%5,%6,%7}, [%8];"
        : "=r"(r0), "=r"(r1), "=r"(r2), "=r"(r3),
          "=r"(r4), "=r"(r5), "=r"(r6), "=r"(r7)
        : "l"(p));
    F8 o;
    o.v[0] = __uint_as_float(r0); o.v[1] = __uint_as_float(r1);
    o.v[2] = __uint_as_float(r2); o.v[3] = __uint_as_float(r3);
    o.v[4] = __uint_as_float(r4); o.v[5] = __uint_as_float(r5);
    o.v[6] = __uint_as_float(r6); o.v[7] = __uint_as_float(r7);
    return o;
}

__device__ __forceinline__ void stg_row(float* p, const F8& a) {
    asm volatile("st.global.L2::evict_first.v8.b32 [%0], {%1,%2,%3,%4,%5,%6,%7,%8};"
        :: "l"(p),
           "r"(__float_as_uint(a.v[0])), "r"(__float_as_uint(a.v[1])),
           "r"(__float_as_uint(a.v[2])), "r"(__float_as_uint(a.v[3])),
           "r"(__float_as_uint(a.v[4])), "r"(__float_as_uint(a.v[5])),
           "r"(__float_as_uint(a.v[6])), "r"(__float_as_uint(a.v[7]))
        : "memory");
}

__global__ __launch_bounds__(256)
void hashgrid_kernel(const float2* __restrict__ x,
                     const float* __restrict__ table,   // 8 floats per row
                     float* __restrict__ out,           // 8 floats per point
                     int n_points)
{
    const unsigned P0 = 73856093u;
    const unsigned P1 = 19349663u;

    int p = blockIdx.x * blockDim.x + threadIdx.x;
    if (p >= n_points) return;

    float2 xp = __ldg(&x[p]);

    // (x+1)*0.5*1024 == (x+1)*512 exactly (power-of-2 scalings are exact in f32),
    // so indices are bit-identical to the reference.
    float fx = (xp.x + 1.0f) * 512.0f;
    float fy = (xp.y + 1.0f) * 512.0f;

    int ix = (int)fx;            // xs >= 0, trunc == floor == astype(int64)
    int iy = (int)fy;
    float wx = fx - (float)ix;
    float wy = fy - (float)iy;

    // hash = (i*P0) ^ (j*P1) mod 2^22 — low 22 bits of uint32 products match int64.
    unsigned hx0 = (unsigned)ix * P0;
    unsigned hx1 = hx0 + P0;
    unsigned hy0 = (unsigned)iy * P1;
    unsigned hy1 = hy0 + P1;

    unsigned i00 = (hx0 ^ hy0) & HASHMAP_MASK;  // (i  , j  )
    unsigned i10 = (hx1 ^ hy0) & HASHMAP_MASK;  // (i+1, j  )
    unsigned i01 = (hx0 ^ hy1) & HASHMAP_MASK;  // (i  , j+1)
    unsigned i11 = (hx1 ^ hy1) & HASHMAP_MASK;  // (i+1, j+1)

    float w00 = (1.0f - wx) * (1.0f - wy);
    float w10 = wx * (1.0f - wy);
    float w01 = (1.0f - wx) * wy;
    float w11 = wx * wy;

    // Issue all four 256-bit gathers back-to-back for MLP=4 before consuming.
    F8 a = ldg_row(table + (size_t)i00 * 8u);
    F8 b = ldg_row(table + (size_t)i10 * 8u);
    F8 c = ldg_row(table + (size_t)i01 * 8u);
    F8 d = ldg_row(table + (size_t)i11 * 8u);

    F8 acc;
#pragma unroll
    for (int f = 0; f < 8; f++)
        acc.v[f] = a.v[f] * w00 + b.v[f] * w10 + c.v[f] * w01 + d.v[f] * w11;

    stg_row(out + (size_t)p * 8u, acc);
}

extern "C" void kernel_launch(void* const* d_in, const int* in_sizes, int n_in,
                              void* d_out, int out_size)
{
    const float2* x    = (const float2*)d_in[0];   // (N_POINTS, 2) float32
    const float* table = (const float*)d_in[1];    // (2^22, 8)  float32
    float* out         = (float*)d_out;            // (N_POINTS, 8) float32

    int n_points = in_sizes[0] / 2;
    int block = 256;
    int grid = (n_points + block - 1) / block;
    if (grid < 1) grid = 1;
    hashgrid_kernel<<<grid, block>>>(x, table, out, n_points);
}